// round 16
// baseline (speedup 1.0000x reference)
#include <cuda_runtime.h>
#include <cstdint>

// Problem constants
#define NB   4
#define CC   64
#define HH   256
#define WW   448
#define HWSZ (HH * WW)            // 114688
#define KCAP 32                   // max entries per target (Poisson(4) tail ~1e-24)

#define NTSP (HWSZ / 32)          // 3584 transpose blocks (32 px each)
#define NBLD (HWSZ / 256)         // 448 build blocks
#define NGTH (HWSZ / 32)          // 3584 gather blocks (32 targets each)
#define NTB  (NTSP + NBLD)        // 4032

// PING-PONG scratch (buf = batch & 1): tb(n) writes buffer n&1 while
// gather(n-1) reads buffer (n-1)&1 in the SAME launch -- disjoint.
// Static zero-init; gather re-zeroes its buffer's g_cnt behind itself, so
// every kernel_launch starts from identical state (graph replays OK).
__device__ float g_tin[2][(size_t)HWSZ * 64];   // [buf][pix][64ch]  2x29.4 MB
__device__ int   g_cnt[2][HWSZ];
__device__ uint2 g_ent[2][(size_t)KCAP * HWSZ]; // [buf][slot][target]

// ---------------------------------------------------------------------------
// tb part A: transpose 32 px x 64 ch tile, NCHW -> channel-last.
// ---------------------------------------------------------------------------
__device__ __forceinline__ void transpose_body(
    const float* __restrict__ inp, float* __restrict__ tin,
    int p0, float (*s)[65])
{
    const int tid  = threadIdx.x;
    const int lane = tid & 31;
    const int wa   = tid >> 5;

    #pragma unroll
    for (int k = 0; k < 8; k++) {
        int ch = wa + k * 8;
        s[lane][ch] = __ldcs(inp + (size_t)ch * HWSZ + p0 + lane);
    }
    __syncthreads();

    float4* tb = reinterpret_cast<float4*>(tin) + (size_t)p0 * 16;
    #pragma unroll
    for (int k = 0; k < 2; k++) {
        int i  = tid + k * 256;
        int px = i >> 4;
        int f4 = i & 15;
        tb[i] = make_float4(s[px][f4 * 4 + 0], s[px][f4 * 4 + 1],
                            s[px][f4 * 4 + 2], s[px][f4 * 4 + 3]);
    }
}

// ---------------------------------------------------------------------------
// tb part B: build per-target entry lists (slot-major layout).
// ---------------------------------------------------------------------------
__device__ __forceinline__ void build_body(
    const float* __restrict__ flow,
    const float* __restrict__ metric,
    int* __restrict__ cnt, uint2* __restrict__ ent, int p0)
{
    const int p = p0 + threadIdx.x;
    const int h = p / WW;
    const int w = p - h * WW;

    float fx = __ldcs(flow + p);
    float fy = __ldcs(flow + HWSZ + p);
    float m  = expf(__ldcs(metric + p));

    float xx  = (float)w + fx;
    float yy  = (float)h + fy;
    float x0f = floorf(xx);
    float y0f = floorf(yy);
    int   x0  = (int)x0f;
    int   y0  = (int)y0f;
    float ax  = xx - x0f;
    float ay  = yy - y0f;

    float wgt[4];
    wgt[0] = (1.f - ax) * (1.f - ay);
    wgt[1] = ax * (1.f - ay);
    wgt[2] = (1.f - ax) * ay;
    wgt[3] = ax * ay;

    #pragma unroll
    for (int j = 0; j < 4; j++) {
        int xi = x0 + (j & 1);
        int yi = y0 + (j >> 1);
        if (((unsigned)xi < (unsigned)WW) && ((unsigned)yi < (unsigned)HH)) {
            int t   = yi * WW + xi;
            int pos = atomicAdd(&cnt[t], 1);
            if (pos < KCAP) {
                ent[(size_t)pos * HWSZ + t] =
                    make_uint2((unsigned)p, __float_as_uint(wgt[j] * m));
            }
        }
    }
}

// ---------------------------------------------------------------------------
// Gather body (R14 known-good): half-warp per target, float4 lanes.
// ---------------------------------------------------------------------------
__device__ __forceinline__ void gather_body(
    float* __restrict__ out,
    const float* __restrict__ tin,
    int* __restrict__ cnt, const uint2* __restrict__ ent,
    int p0, char* sraw)
{
    float4 (*s_out4)[17] = reinterpret_cast<float4(*)[17]>(sraw);  // 8704 B
    int*   s_cnt = reinterpret_cast<int*>(sraw + 8704);            // 128 B

    const int tid  = threadIdx.x;
    const int lane = tid & 31;
    const int wa   = tid >> 5;          // 8 warps

    if (tid < 32) {
        int c = cnt[p0 + tid];
        s_cnt[tid] = (c < KCAP) ? c : KCAP;
        cnt[p0 + tid] = 0;              // restore for next use / replay
    }
    __syncthreads();

    const int tbase = wa * 4;
    const int half  = lane >> 4;
    const int c4    = lane & 15;

    const int n0 = s_cnt[tbase + 0];
    const int n1 = s_cnt[tbase + 1];
    const int n2 = s_cnt[tbase + 2];
    const int n3 = s_cnt[tbase + 3];
    const int nmax = max(max(n0, n1), max(n2, n3));

    const int nlA = half ? n1 : n0;
    const int nlB = half ? n3 : n2;

    const uint2* __restrict__ ebA = ent + p0 + tbase + half;
    const uint2* __restrict__ ebB = ent + p0 + tbase + 2 + half;

    const float4* __restrict__ tin4 = reinterpret_cast<const float4*>(tin);

    float4 accA = make_float4(0.f, 0.f, 0.f, 0.f);
    float4 accB = make_float4(0.f, 0.f, 0.f, 0.f);
    float  swA = 0.f, swB = 0.f;

    #define GPAIR(EB, NL, ACC, SW, I)                                         \
    {                                                                         \
        uint2 e   = __ldcs((EB) + (size_t)(I) * HWSZ);                        \
        bool  liv = ((I) < (NL));                                             \
        float wv  = liv ? __uint_as_float(e.y) : 0.f;                         \
        unsigned sx = liv ? e.x : 0u;                                         \
        float4 v  = tin4[(size_t)sx * 16 + c4];                               \
        (ACC).x += wv * v.x;                                                  \
        (ACC).y += wv * v.y;                                                  \
        (ACC).z += wv * v.z;                                                  \
        (ACC).w += wv * v.w;                                                  \
        (SW)    += wv;                                                        \
    }

    #pragma unroll
    for (int i = 0; i < 4; i++) {
        GPAIR(ebA, nlA, accA, swA, i)
        GPAIR(ebB, nlB, accB, swB, i)
    }
    if (nmax > 4) {
        #pragma unroll
        for (int i = 4; i < 8; i++) {
            GPAIR(ebA, nlA, accA, swA, i)
            GPAIR(ebB, nlB, accB, swB, i)
        }
    }
    if (nmax > 8) {
        const int npA = max(n0, n1);
        const int npB = max(n2, n3);
        for (int i = 8; i < npA; i++) GPAIR(ebA, nlA, accA, swA, i)
        for (int i = 8; i < npB; i++) GPAIR(ebB, nlB, accB, swB, i)
    }
    #undef GPAIR

    const float invA = (swA == 0.f) ? 1.f : (1.f / swA);
    const float invB = (swB == 0.f) ? 1.f : (1.f / swB);
    s_out4[tbase + half][c4] =
        make_float4(accA.x * invA, accA.y * invA, accA.z * invA, accA.w * invA);
    s_out4[tbase + 2 + half][c4] =
        make_float4(accB.x * invB, accB.y * invB, accB.z * invB, accB.w * invB);
    __syncthreads();

    const float* s = reinterpret_cast<const float*>(s_out4);
    float* ob = out + p0 + lane;
    #pragma unroll
    for (int k = 0; k < 8; k++) {
        int c = wa + k * 8;
        __stcs(ob + (size_t)c * HWSZ, s[lane * 68 + c]);
    }
}

// ---------------------------------------------------------------------------
// One pipeline step: blocks [0,NTB) run tb for batch sn into buffer sn&1;
// blocks [NTB, NTB+NGTH) run gather for batch gn from buffer gn&1.
// Disjoint buffers -> no intra-launch ordering needed.
// ---------------------------------------------------------------------------
__global__ __launch_bounds__(256) void step_kernel(
    const float* __restrict__ inp,      // null -> skip tb
    const float* __restrict__ flow,
    const float* __restrict__ metric,
    float* __restrict__ out,            // null -> skip gather
    int sbuf, int gbuf)
{
    __shared__ alignas(16) char sraw[8832];

    if (blockIdx.x < NTB) {
        if (inp) {
            if (blockIdx.x < NTSP) {
                transpose_body(inp, g_tin[sbuf], blockIdx.x * 32,
                               reinterpret_cast<float(*)[65]>(sraw));
            } else {
                build_body(flow, metric, g_cnt[sbuf], g_ent[sbuf],
                           (blockIdx.x - NTSP) * 256);
            }
        }
    } else {
        if (out) {
            gather_body(out, g_tin[gbuf], g_cnt[gbuf], g_ent[gbuf],
                        (blockIdx.x - NTB) * 32, sraw);
        }
    }
}

// ---------------------------------------------------------------------------
extern "C" void kernel_launch(void* const* d_in, const int* in_sizes, int n_in,
                              void* d_out, int out_size)
{
    const float* inp    = (const float*)d_in[0];
    const float* flow   = (const float*)d_in[1];
    const float* metric = (const float*)d_in[2];
    float* out = (float*)d_out;

    for (int step = 0; step <= NB; step++) {
        const int sn = step;        // batch fed to tb
        const int gn = step - 1;    // batch being gathered

        const float* si = (sn < NB) ? inp    + (size_t)sn * CC * HWSZ : nullptr;
        const float* sf = (sn < NB) ? flow   + (size_t)sn * 2  * HWSZ : nullptr;
        const float* sm = (sn < NB) ? metric + (size_t)sn * HWSZ      : nullptr;
        float*       go = (gn >= 0) ? out    + (size_t)gn * CC * HWSZ : nullptr;

        step_kernel<<<NTB + NGTH, 256>>>(si, sf, sm, go,
                                         sn & 1, (gn >= 0) ? (gn & 1) : 0);
    }
}